// round 1
// baseline (speedup 1.0000x reference)
#include <cuda_runtime.h>
#include <math.h>

#define Bb 4
#define Hh 96
#define Ww 96
#define Cc 256
#define Ff 256

// scratch for offset-conv output: per pixel 27 values:
// [0..8]=dy, [9..17]=dx, [18..26]=sigmoid(mask)
__device__ float g_om[Bb * Hh * Ww * 27];

// ---------------------------------------------------------------------------
// Kernel A: 3x3 SAME conv, C=256 -> 27, + bias, sigmoid on channels 18..26.
// Block: 32 pixels along W (grid.x=3), one (b,h) row per (grid.z, grid.y).
// blockDim=128: tid%32 = oc (27 active), tid/32 = pixel group (4 groups x 8 px)
// ---------------------------------------------------------------------------
__global__ __launch_bounds__(128) void offset_conv_kernel(
    const float* __restrict__ x, const float* __restrict__ w_off,
    const float* __restrict__ b_off)
{
    __shared__ __align__(16) float xs_s[16][36];  // [c_chunk][px] padded (bank-safe)
    __shared__ float ws_s[16][28];                // [c_chunk][oc]

    const int w0 = blockIdx.x * 32;
    const int h  = blockIdx.y;
    const int b  = blockIdx.z;
    const int tid = threadIdx.x;
    const int oc = tid & 31;
    const int pg = tid >> 5;   // 0..3

    float acc[8];
#pragma unroll
    for (int j = 0; j < 8; j++) acc[j] = 0.f;

    for (int t = 0; t < 9; t++) {
        const int ky = t / 3, kx = t % 3;
        const int y = h + ky - 1;
        if (y < 0 || y >= Hh) continue;   // uniform across block -> sync-safe
        const float* xrow = x + ((size_t)(b * Hh + y) * Ww) * Cc;

        for (int cc = 0; cc < 16; cc++) {
            __syncthreads();
            // stage x patch chunk: 16 channels x 32 pixels
            {
                const int ci  = tid & 15;
                const int pxg = tid >> 4;  // 0..7
#pragma unroll
                for (int j = 0; j < 4; j++) {
                    const int px = pxg + j * 8;
                    const int xc = w0 + px + kx - 1;
                    float v = 0.f;
                    if (xc >= 0 && xc < Ww) v = xrow[xc * Cc + cc * 16 + ci];
                    xs_s[ci][px] = v;
                }
            }
            // stage weights chunk: 16 channels x 27 oc
            for (int idx = tid; idx < 16 * 27; idx += 128) {
                const int ci = idx / 27, o = idx % 27;
                ws_s[ci][o] = w_off[(t * Cc + cc * 16 + ci) * 27 + o];
            }
            __syncthreads();

            if (oc < 27) {
#pragma unroll
                for (int ci = 0; ci < 16; ci++) {
                    const float wv = ws_s[ci][oc];
                    const float* xr = &xs_s[ci][pg * 8];
                    const float4 a  = *(const float4*)(xr);
                    const float4 c2 = *(const float4*)(xr + 4);
                    acc[0] += a.x  * wv; acc[1] += a.y  * wv;
                    acc[2] += a.z  * wv; acc[3] += a.w  * wv;
                    acc[4] += c2.x * wv; acc[5] += c2.y * wv;
                    acc[6] += c2.z * wv; acc[7] += c2.w * wv;
                }
            }
        }
    }

    if (oc < 27) {
        const float bo = b_off[oc];
#pragma unroll
        for (int j = 0; j < 8; j++) {
            float v = acc[j] + bo;
            if (oc >= 18) v = 1.f / (1.f + expf(-v));   // sigmoid for mask
            const int px = pg * 8 + j;
            g_om[((size_t)((b * Hh + h) * Ww + w0 + px)) * 27 + oc] = v;
        }
    }
}

// ---------------------------------------------------------------------------
// Kernel B: deformable sampling + [32 px, 2304] x [2304, 256] GEMM per block.
// blockDim=256: tx = tid&63 -> f group (4 f), py = tid>>6 -> 8-pixel group.
// Each thread: acc[8 px][4 f].
// ---------------------------------------------------------------------------
__global__ __launch_bounds__(256) void dcn_main_kernel(
    const float* __restrict__ x, const float* __restrict__ w_conv,
    const float* __restrict__ b_conv, float* __restrict__ out)
{
    __shared__ __align__(16) float w_s[32 * 256];   // [ci][f]   32 KB
    __shared__ float s_s[32 * 33];                  // [ci][px]  padded (bank-safe)
    __shared__ float4 mw[288];                      // per (px,tap): 4 corner weights
    __shared__ int4   mi[288];                      // per (px,tap): 4 corner bases

    const int w0 = blockIdx.x * 32;
    const int h  = blockIdx.y;
    const int b  = blockIdx.z;
    const int tid = threadIdx.x;

    // ---- bilinear meta for 32 px x 9 taps ----
    for (int e = tid; e < 288; e += 256) {
        const int px = e / 9, k = e % 9;
        const int p = (b * Hh + h) * Ww + w0 + px;
        const float* om = g_om + (size_t)p * 27;
        const float dy = om[k], dx = om[9 + k], mask = om[18 + k];
        const int ky = k / 3, kx = k % 3;
        const float ys = (float)(h + ky - 1) + dy;
        const float xs = (float)(w0 + px + kx - 1) + dx;
        const float y0f = floorf(ys), x0f = floorf(xs);
        const float wy1 = ys - y0f, wx1 = xs - x0f;
        const float wy0 = 1.f - wy1, wx0 = 1.f - wx1;
        const int y0 = (int)y0f, x0i = (int)x0f;
        const int y1 = y0 + 1,   x1i = x0i + 1;
        const bool vy0 = (y0  >= 0) && (y0  < Hh);
        const bool vy1 = (y1  >= 0) && (y1  < Hh);
        const bool vx0 = (x0i >= 0) && (x0i < Ww);
        const bool vx1 = (x1i >= 0) && (x1i < Ww);
        const float w00 = (vy0 && vx0) ? wy0 * wx0 * mask : 0.f;
        const float w01 = (vy0 && vx1) ? wy0 * wx1 * mask : 0.f;
        const float w10 = (vy1 && vx0) ? wy1 * wx0 * mask : 0.f;
        const float w11 = (vy1 && vx1) ? wy1 * wx1 * mask : 0.f;
        const int y0c = min(max(y0, 0), Hh - 1), y1c = min(max(y1, 0), Hh - 1);
        const int x0c = min(max(x0i, 0), Ww - 1), x1c = min(max(x1i, 0), Ww - 1);
        const int r0 = (b * Hh + y0c) * Ww, r1 = (b * Hh + y1c) * Ww;
        mw[e] = make_float4(w00, w01, w10, w11);
        mi[e] = make_int4((r0 + x0c) * Cc, (r0 + x1c) * Cc,
                          (r1 + x0c) * Cc, (r1 + x1c) * Cc);
    }
    __syncthreads();

    float acc[8][4];
#pragma unroll
    for (int i = 0; i < 8; i++)
#pragma unroll
        for (int j = 0; j < 4; j++) acc[i][j] = 0.f;

    const int tx  = tid & 63;    // f group
    const int py  = tid >> 6;    // pixel group (0..3)
    const int cis = tid & 31;    // staging: channel-in-chunk
    const int pxb = tid >> 5;    // staging: pixel base (0..7)

    for (int k = 0; k < 9; k++) {
        for (int cc = 0; cc < 8; cc++) {
            __syncthreads();
            // ---- stage w_conv chunk: 32 c x 256 f ----
            {
                const float4* wsrc =
                    (const float4*)(w_conv + (size_t)(k * Cc + cc * 32) * Ff);
                float4* wdst = (float4*)w_s;
#pragma unroll
                for (int i = 0; i < 8; i++)
                    wdst[tid + i * 256] = wsrc[tid + i * 256];
            }
            // ---- stage sampled tile: 32 c x 32 px ----
            {
                const int c = cc * 32 + cis;
#pragma unroll
                for (int j = 0; j < 4; j++) {
                    const int px = pxb + j * 8;
                    const int e = px * 9 + k;
                    const float4 wv = mw[e];
                    const int4   a  = mi[e];
                    float v = wv.x * x[a.x + c];
                    v += wv.y * x[a.y + c];
                    v += wv.z * x[a.z + c];
                    v += wv.w * x[a.w + c];
                    s_s[cis * 33 + px] = v;
                }
            }
            __syncthreads();
            // ---- FFMA core: 32 c x (8 px x 4 f) per thread ----
#pragma unroll 8
            for (int ci = 0; ci < 32; ci++) {
                const float4 wv = *(const float4*)&w_s[ci * 256 + tx * 4];
                const float* sr = &s_s[ci * 33 + py * 8];
#pragma unroll
                for (int i = 0; i < 8; i++) {
                    const float sv = sr[i];
                    acc[i][0] += sv * wv.x;
                    acc[i][1] += sv * wv.y;
                    acc[i][2] += sv * wv.z;
                    acc[i][3] += sv * wv.w;
                }
            }
        }
    }

    // ---- epilogue: + bias, store ----
    const float4 bc = *(const float4*)(b_conv + tx * 4);
    const size_t base = ((size_t)((b * Hh + h) * Ww + w0)) * Ff;
#pragma unroll
    for (int i = 0; i < 8; i++) {
        const int px = py * 8 + i;
        float4 o;
        o.x = acc[i][0] + bc.x;
        o.y = acc[i][1] + bc.y;
        o.z = acc[i][2] + bc.z;
        o.w = acc[i][3] + bc.w;
        *(float4*)(out + base + (size_t)px * Ff + tx * 4) = o;
    }
}

// ---------------------------------------------------------------------------
extern "C" void kernel_launch(void* const* d_in, const int* in_sizes, int n_in,
                              void* d_out, int out_size)
{
    (void)in_sizes; (void)n_in; (void)out_size;
    const float* x      = (const float*)d_in[0];
    const float* w_off  = (const float*)d_in[1];
    const float* b_off  = (const float*)d_in[2];
    const float* w_conv = (const float*)d_in[3];
    const float* b_conv = (const float*)d_in[4];
    float* out = (float*)d_out;

    dim3 gA(3, 96, 4);
    offset_conv_kernel<<<gA, 128>>>(x, w_off, b_off);
    dim3 gB(3, 96, 4);
    dcn_main_kernel<<<gB, 256>>>(x, w_conv, b_conv, out);
}